// round 5
// baseline (speedup 1.0000x reference)
#include <cuda_runtime.h>
#include <math.h>

// Fixed problem shapes
#define BB 16
#define HH 256
#define WW 256
#define SS 24
#define PS (HH * WW)             // per-channel plane stride
#define NPIX (BB * HH * WW)      // 1,048,576
#define NBLK 2048                // blocks: 2 rows per block
#define EPSF 1e-6f
#define WGRAD 0.05f

typedef unsigned long long ull;

__device__ float2 g_partials[NBLK];
__device__ unsigned int g_count = 0;

// ---------- packed f32x2 + MUFU helpers ----------
__device__ __forceinline__ ull pack2(float lo, float hi) {
    ull r; asm("mov.b64 %0, {%1, %2};" : "=l"(r) : "f"(lo), "f"(hi)); return r;
}
__device__ __forceinline__ void unpack2(ull v, float& lo, float& hi) {
    asm("mov.b64 {%0, %1}, %2;" : "=f"(lo), "=f"(hi) : "l"(v));
}
__device__ __forceinline__ ull fma2(ull a, ull b, ull c) {
    ull r; asm("fma.rn.f32x2 %0, %1, %2, %3;" : "=l"(r) : "l"(a), "l"(b), "l"(c)); return r;
}
__device__ __forceinline__ ull mul2(ull a, ull b) {
    ull r; asm("mul.rn.f32x2 %0, %1, %2;" : "=l"(r) : "l"(a), "l"(b)); return r;
}
__device__ __forceinline__ float sqrta(float x) {
    float r; asm("sqrt.approx.f32 %0, %1;" : "=f"(r) : "f"(x)); return r;
}
__device__ __forceinline__ float rsqrta(float x) {
    float r; asm("rsqrt.approx.f32 %0, %1;" : "=f"(r) : "f"(x)); return r;
}

// acos on [0,1]: deg-7 minimax, abs err ~2e-8 (validated rel_err 0.0)
__device__ __forceinline__ float acos_fast(float x) {
    float p = fmaf(x, -0.0012624911f, 0.0066700901f);
    p = fmaf(x, p, -0.0170881256f);
    p = fmaf(x, p,  0.0308918810f);
    p = fmaf(x, p, -0.0501743046f);
    p = fmaf(x, p,  0.0889789874f);
    p = fmaf(x, p, -0.2145988016f);
    p = fmaf(x, p,  1.5707963050f);
    return sqrta(1.0f - x) * p;
}

__global__ __launch_bounds__(256, 6) void fused_loss_kernel(
    const float* __restrict__ qp,
    const float* __restrict__ qt,
    const float* __restrict__ syms,
    float* __restrict__ out)
{
    // Sign-adjusted symmetry splats, packed 2-wide
    __shared__ ulonglong2 s2[SS][2];
    __shared__ float2 wsum[8];
    __shared__ bool amLast;

    const int tid = threadIdx.x;
    if (tid < SS) {
        float a =  syms[tid * 4 + 0];
        float b = -syms[tid * 4 + 1];
        float c = -syms[tid * 4 + 2];
        float d = -syms[tid * 4 + 3];
        s2[tid][0] = make_ulonglong2(pack2(a, a), pack2(b, b));
        s2[tid][1] = make_ulonglong2(pack2(c, c), pack2(d, d));
    }
    __syncthreads();

    const ull NEG1 = pack2(-1.0f, -1.0f);
    const ull EPS2 = pack2(EPSF, EPSF);

    // 2 rows per block, 128 threads per row, 2 pixels per thread (float2)
    const int row = (blockIdx.x << 1) + (tid >> 7);   // row = b*HH + h
    const int t   = tid & 127;
    const int b   = row >> 8;
    const int h   = row & (HH - 1);
    const int base = b * 4 * PS + h * WW + (t << 1);
    const int dh  = (h < HH - 1) ? WW : -WW;          // mirrored edge: |diff| identical
    const bool hasr = (t < 127);

    // ---- per-channel: load + packed gradient term; retain centers ----
    float2 P2[4], T2[4];
    float gsum = 0.0f;
#pragma unroll
    for (int c = 0; c < 4; c++) {
        const float* pp = qp + base + c * PS;
        const float* tt = qt + base + c * PS;
        float2 p  = __ldg((const float2*)pp);
        float2 tq = __ldg((const float2*)tt);
        float2 pd = __ldg((const float2*)(pp + dh));
        float2 td = __ldg((const float2*)(tt + dh));
        // right neighbor of px1; mirrored at w=255 (|diff| identical)
        float pr = hasr ? __ldg(pp + 2) : p.x;
        float tr = hasr ? __ldg(tt + 2) : tq.x;

        ull pc  = pack2(p.x, p.y);
        ull prp = pack2(p.y, pr);
        ull pdp = pack2(pd.x, pd.y);
        ull tc  = pack2(tq.x, tq.y);
        ull trp = pack2(tq.y, tr);
        ull tdp = pack2(td.x, td.y);

        ull gxp = fma2(pc, NEG1, prp);
        ull gyp = fma2(pc, NEG1, pdp);
        ull gxt = fma2(tc, NEG1, trp);
        ull gyt = fma2(tc, NEG1, tdp);

        ull sp = fma2(gxp, gxp, fma2(gyp, gyp, EPS2));
        ull st = fma2(gxt, gxt, fma2(gyt, gyt, EPS2));

        float a0, a1, b0, b1;
        unpack2(sp, a0, a1);
        unpack2(st, b0, b1);
        gsum += fabsf(sqrta(a0) - sqrta(b0));
        gsum += fabsf(sqrta(a1) - sqrta(b1));

        P2[c] = p; T2[c] = tq;
    }

    // ---- relative quaternion on RAW quats (normalization folded out) ----
    // r(p,t) is bilinear: r(p/|p|, t/|t|) = r(p,t) * (1/|p|)(1/|t|).
    ull A0 = pack2(P2[0].x, P2[0].y), A1 = pack2(P2[1].x, P2[1].y);
    ull A2 = pack2(P2[2].x, P2[2].y), A3 = pack2(P2[3].x, P2[3].y);
    ull B0 = pack2(T2[0].x, T2[0].y), B1 = pack2(T2[1].x, T2[1].y);
    ull B2 = pack2(T2[2].x, T2[2].y), B3 = pack2(T2[3].x, T2[3].y);

    ull dp = fma2(A0, A0, fma2(A1, A1, fma2(A2, A2, mul2(A3, A3))));
    ull dt = fma2(B0, B0, fma2(B1, B1, fma2(B2, B2, mul2(B3, B3))));
    float dp0, dp1, dt0, dt1;
    unpack2(dp, dp0, dp1); unpack2(dt, dt0, dt1);
    float s0 = rsqrta(dp0) * rsqrta(dt0);
    float s1 = rsqrta(dp1) * rsqrta(dt1);

    ull B0n = mul2(B0, NEG1);
    ull B1n = mul2(B1, NEG1);
    ull B2n = mul2(B2, NEG1);
    ull B3n = mul2(B3, NEG1);

    ull RW = fma2(B0,  A0, fma2(B1,  A1, fma2(B2,  A2, mul2(B3,  A3))));
    ull RX = fma2(B0n, A1, fma2(B1,  A0, fma2(B2n, A3, mul2(B3,  A2))));
    ull RY = fma2(B0n, A2, fma2(B1,  A3, fma2(B2,  A0, mul2(B3n, A1))));
    ull RZ = fma2(B0n, A3, fma2(B1n, A2, fma2(B2,  A1, mul2(B3,  A0))));

    // ---- 24-symmetry max|dot| (packed; |x| folds into FMNMX) ----
    float m0 = 0.0f, m1 = 0.0f;
#pragma unroll
    for (int sy = 0; sy < SS; sy++) {
        ulonglong2 vab = s2[sy][0];   // {x,x}, {y,y}
        ulonglong2 vcd = s2[sy][1];   // {z,z}, {w,w}
        ull d = fma2(RW, vab.x, fma2(RX, vab.y, fma2(RY, vcd.x, mul2(RZ, vcd.y))));
        float a, bb;
        unpack2(d, a, bb);
        m0 = fmaxf(m0, fabsf(a));
        m1 = fmaxf(m1, fabsf(bb));
    }
    const float CL = 1.0f - EPSF;
    float rot = acos_fast(fminf(m0 * s0, CL)) + acos_fast(fminf(m1 * s1, CL));
    rot *= 2.0f;

    // ---- block reduction ----
    float r = rot, g = gsum;
#pragma unroll
    for (int o = 16; o > 0; o >>= 1) {
        r += __shfl_xor_sync(0xFFFFFFFFu, r, o);
        g += __shfl_xor_sync(0xFFFFFFFFu, g, o);
    }
    const int lane = tid & 31;
    const int warp = tid >> 5;
    if (lane == 0) wsum[warp] = make_float2(r, g);
    __syncthreads();
    if (warp == 0) {
        float2 v = (lane < 8) ? wsum[lane] : make_float2(0.0f, 0.0f);
        float rr = v.x, gg = v.y;
#pragma unroll
        for (int o = 4; o > 0; o >>= 1) {
            rr += __shfl_xor_sync(0xFFFFFFFFu, rr, o);
            gg += __shfl_xor_sync(0xFFFFFFFFu, gg, o);
        }
        if (lane == 0) {
            g_partials[blockIdx.x] = make_float2(rr, gg);
            __threadfence();
            unsigned int c = atomicAdd(&g_count, 1u);
            amLast = (c == NBLK - 1);
        }
    }
    __syncthreads();

    // ---- last block: grid-wide finish (deterministic fixed-order sum) ----
    if (amLast) {
        float r2 = 0.0f, g2 = 0.0f;
#pragma unroll
        for (int i = tid; i < NBLK; i += 256) {
            float2 v = __ldcg(&g_partials[i]);
            r2 += v.x; g2 += v.y;
        }
#pragma unroll
        for (int o = 16; o > 0; o >>= 1) {
            r2 += __shfl_xor_sync(0xFFFFFFFFu, r2, o);
            g2 += __shfl_xor_sync(0xFFFFFFFFu, g2, o);
        }
        if (lane == 0) wsum[warp] = make_float2(r2, g2);
        __syncthreads();
        if (tid == 0) {
            float rr = 0.0f, gg = 0.0f;
#pragma unroll
            for (int i = 0; i < 8; i++) { rr += wsum[i].x; gg += wsum[i].y; }
            out[0] = rr / (float)NPIX + WGRAD * (gg / (float)(4 * NPIX));
            g_count = 0;   // reset for next graph replay
        }
    }
}

extern "C" void kernel_launch(void* const* d_in, const int* in_sizes, int n_in,
                              void* d_out, int out_size)
{
    const float* qp   = (const float*)d_in[0];
    const float* qt   = (const float*)d_in[1];
    const float* syms = (const float*)d_in[2];
    float* out = (float*)d_out;

    fused_loss_kernel<<<NBLK, 256>>>(qp, qt, syms, out);
}